// round 7
// baseline (speedup 1.0000x reference)
#include <cuda_runtime.h>
#include <cuda_bf16.h>

// S4D: out[h,l] = 2*Re( sum_n Ceff[h,n] * exp(dtA[h,n]*l) )
// Kernel 1: precompute per-(h,n) recurrence params (libm trig, trivially parallel).
// Kernel 2: per-n real 2-term recurrence y_{l+2}=a*y_{l+1}-b*y_l, packed f32x2
//   over n-pairs, t-outer/p-inner for ILP. 128 thr/block: group g owns 8 n-pairs;
//   per-chunk partial sums combined via smem with ALTERNATING producer/consumer
//   roles (balanced store path). No setup phase, no pre-main barriers.

#define HH      1024
#define NH      32
#define LL      4096
#define THREADS 128
#define LTH     64          // threads spanning l per group
#define TPT     64          // l-values per thread
#define CH      8           // l per chunk
#define NCH     (TPT / CH)  // 8 chunks
#define NPG     8           // n-pairs per group
#define NPAIR   (NH / 2)    // 16 pairs per h

#define TWO_PI      6.283185307179586f
#define INV_TWO_PI  0.15915494309189535f

// Packed params: for (h, pair): [0]=(a0,a1,nb0,nb1) [1]=(ur0,ui0,ur1,ui1)
//                               [2]=(uwr0,uwi0,uwr1,uwi1) [3]=(re0,turn0,re1,turn1)
__device__ float4 g_params[HH * NPAIR * 4];

union F2U { float2 f; unsigned long long u; };

__device__ __forceinline__ float2 f2_fma(float2 a, float2 b, float2 c) {
    F2U A, B, C, D; A.f = a; B.f = b; C.f = c;
    asm("fma.rn.f32x2 %0, %1, %2, %3;" : "=l"(D.u) : "l"(A.u), "l"(B.u), "l"(C.u));
    return D.f;
}
__device__ __forceinline__ float2 f2_mul(float2 a, float2 b) {
    F2U A, B, D; A.f = a; B.f = b;
    asm("mul.rn.f32x2 %0, %1, %2;" : "=l"(D.u) : "l"(A.u), "l"(B.u));
    return D.f;
}
__device__ __forceinline__ float2 f2_add(float2 a, float2 b) {
    F2U A, B, D; A.f = a; B.f = b;
    asm("add.rn.f32x2 %0, %1, %2;" : "=l"(D.u) : "l"(A.u), "l"(B.u));
    return D.f;
}

// ---------- kernel 1: per-(h,n) parameter precompute ----------
__global__ void s4d_setup(const float* __restrict__ C_param,
                          const float* __restrict__ log_dt,
                          const float* __restrict__ log_A_real,
                          const float* __restrict__ A_imag)
{
    int idx = blockIdx.x * blockDim.x + threadIdx.x;   // (h, n)
    if (idx >= HH * NH) return;
    const int h = idx >> 5;
    const int n = idx & 31;
    const int hn = idx;

    float dt = expf(log_dt[h]);
    float Ar = -expf(log_A_real[hn]);
    float Ai = A_imag[hn];
    float re = Ar * dt;                       // Re(dtA) (<0)
    float im = Ai * dt;                       // Im(dtA)
    float er = expf(re);
    float si, co; sincosf(im, &si, &co);
    float wr = er * co, wi = er * si;         // w = exp(dtA)
    float a  = 2.0f * wr;
    float nb = -fmaf(wr, wr, wi * wi);        // -|w|^2
    // u = 2*C*(w-1)/A
    float numr = wr - 1.0f, numi = wi;
    float invd = 1.0f / fmaf(Ar, Ar, Ai * Ai);
    float tr = (numr * Ar + numi * Ai) * invd;
    float ti = (numi * Ar - numr * Ai) * invd;
    float Cr = C_param[2 * hn + 0];
    float Ci = C_param[2 * hn + 1];
    float ur  = 2.0f * (Cr * tr - Ci * ti);
    float ui  = 2.0f * (Cr * ti + Ci * tr);
    float uwr = ur * wr - ui * wi;            // u*w
    float uwi = ur * wi + ui * wr;
    float turn = im * INV_TWO_PI;

    const int pair = n >> 1;
    const int k    = n & 1;
    float* base = (float*)&g_params[(h * NPAIR + pair) * 4];
    // [0]: a0,a1,nb0,nb1
    base[0 + k]      = a;
    base[2 + k]      = nb;
    // [1]: ur0,ui0,ur1,ui1
    base[4 + 2 * k]     = ur;
    base[4 + 2 * k + 1] = ui;
    // [2]: uwr0,uwi0,uwr1,uwi1
    base[8 + 2 * k]     = uwr;
    base[8 + 2 * k + 1] = uwi;
    // [3]: re0,turn0,re1,turn1
    base[12 + 2 * k]     = re;
    base[12 + 2 * k + 1] = turn;
}

// ---------- kernel 2: main recurrence ----------
__global__ __launch_bounds__(THREADS)
void s4d_main(float* __restrict__ out)        // (H, L)
{
    __shared__ float s_red[2][LTH][CH];       // double-buffered partials

    const int h    = blockIdx.x;
    const int tid  = threadIdx.x;
    const int grp  = tid >> 6;                // 0/1: which 8 n-pairs
    const int lane = tid & 63;                // which l-range

    // ---- load params + seed recurrence at l0 = lane*TPT ----
    const float l0 = (float)(lane * TPT);
    const int pbase = (h * NPAIR + grp * NPG) * 4;
    float2 Yp[NPG], Yc[NPG], A2[NPG], NB[NPG];

    #pragma unroll
    for (int p = 0; p < NPG; p++) {
        float4 f0 = __ldg(&g_params[pbase + 4 * p + 0]);   // a0,a1,nb0,nb1
        float4 f1 = __ldg(&g_params[pbase + 4 * p + 1]);   // ur0,ui0,ur1,ui1
        float4 f2 = __ldg(&g_params[pbase + 4 * p + 2]);   // uwr0,uwi0,uwr1,uwi1
        float4 f3 = __ldg(&g_params[pbase + 4 * p + 3]);   // re0,turn0,re1,turn1
        A2[p] = make_float2(f0.x, f0.y);
        NB[p] = make_float2(f0.z, f0.w);

        // k = 0
        float amp0   = __expf(f3.x * l0);
        float turns0 = f3.y * l0;
        float fr0    = turns0 - truncf(turns0);
        float s0, c0; __sincosf(fr0 * TWO_PI, &s0, &c0);
        float y00 = amp0 * (f1.x * c0 - f1.y * s0);        // Re(u*w^{l0})
        float y10 = amp0 * (f2.x * c0 - f2.y * s0);        // Re(u*w^{l0+1})
        // k = 1
        float amp1   = __expf(f3.z * l0);
        float turns1 = f3.w * l0;
        float fr1    = turns1 - truncf(turns1);
        float s1, c1; __sincosf(fr1 * TWO_PI, &s1, &c1);
        float y01 = amp1 * (f1.z * c1 - f1.w * s1);
        float y11 = amp1 * (f2.z * c1 - f2.w * s1);

        Yp[p] = make_float2(y00, y01);
        Yc[p] = make_float2(y10, y11);
    }

    float* orow = out + (size_t)h * LL + lane * TPT;

    // ---- main loop: 8 chunks of 8 l-values ----
    #pragma unroll 1
    for (int c = 0; c < NCH; c++) {
        float2 acc[CH];
        #pragma unroll
        for (int t = 0; t < CH; t++) acc[t] = make_float2(0.0f, 0.0f);

        // t-outer / p-inner: consecutive instrs hit independent chains
        #pragma unroll
        for (int t = 0; t < CH; t++) {
            #pragma unroll
            for (int p = 0; p < NPG; p++) {
                acc[t] = f2_add(acc[t], Yp[p]);
                float2 tmp = f2_mul(NB[p], Yp[p]);     // -b * y_l
                float2 y2  = f2_fma(A2[p], Yc[p], tmp);
                Yp[p] = Yc[p]; Yc[p] = y2;
            }
        }

        float r[CH];
        #pragma unroll
        for (int t = 0; t < CH; t++) r[t] = acc[t].x + acc[t].y;

        // alternate producer/consumer by chunk parity (balanced store path)
        const int buf = c & 1;
        const int producer = c & 1;               // grp==producer writes smem
        if (grp == producer) {
            *reinterpret_cast<float4*>(&s_red[buf][lane][0]) =
                make_float4(r[0], r[1], r[2], r[3]);
            *reinterpret_cast<float4*>(&s_red[buf][lane][4]) =
                make_float4(r[4], r[5], r[6], r[7]);
        }
        __syncthreads();
        if (grp != producer) {
            float4 p0 = *reinterpret_cast<const float4*>(&s_red[buf][lane][0]);
            float4 p1 = *reinterpret_cast<const float4*>(&s_red[buf][lane][4]);
            float4 o0 = make_float4(r[0] + p0.x, r[1] + p0.y,
                                    r[2] + p0.z, r[3] + p0.w);
            float4 o1 = make_float4(r[4] + p1.x, r[5] + p1.y,
                                    r[6] + p1.z, r[7] + p1.w);
            *reinterpret_cast<float4*>(orow + c * CH)     = o0;
            *reinterpret_cast<float4*>(orow + c * CH + 4) = o1;
        }
    }
}

extern "C" void kernel_launch(void* const* d_in, const int* in_sizes, int n_in,
                              void* d_out, int out_size) {
    const float* C_param    = (const float*)d_in[0];
    const float* log_dt     = (const float*)d_in[1];
    const float* log_A_real = (const float*)d_in[2];
    const float* A_imag     = (const float*)d_in[3];
    float* out = (float*)d_out;

    s4d_setup<<<(HH * NH + 255) / 256, 256>>>(C_param, log_dt, log_A_real, A_imag);
    s4d_main<<<HH, THREADS>>>(out);
}